// round 1
// baseline (speedup 1.0000x reference)
#include <cuda_runtime.h>

#define N_NODES 8192
#define N_EDGES 16384

// ---------------- scratch (device globals; no allocs allowed) ----------------
__device__ __align__(16) float g_bo[N_EDGES * 4];   // bo[e][d]
__device__ __align__(16) float g_bi[N_EDGES * 4];   // bi[e][d]
__device__ __align__(16) float g_so[N_EDGES];       // per-edge scalar for Ri side
__device__ __align__(16) float g_si[N_EDGES];       // per-edge scalar for Ro side

// ---------------- kernel 0: zero accumulators (graph replays!) ---------------
__global__ void zero_kernel() {
    int i = blockIdx.x * blockDim.x + threadIdx.x;
    if (i < N_EDGES * 4) {
        g_bo[i] = 0.0f;
        g_bi[i] = 0.0f;
    }
}

// ---------------- kernel 1: bo = Ro^T X, bi = Ri^T X (column reduction) ------
// Grid: (E/(128*4), NCHUNK). Each thread owns 4 consecutive e (one float4 per
// row), loops over its n-chunk, accumulates 4x4 outer products in registers,
// then REDG-accumulates into g_bo/g_bi.
#define K1_THREADS 128
#define K1_NCHUNK  16
#define K1_NPB     (N_NODES / K1_NCHUNK)   // 512 rows per block

#define FMA4(acc, s, v) \
    acc.x += (s) * (v).x; acc.y += (s) * (v).y; \
    acc.z += (s) * (v).z; acc.w += (s) * (v).w;

__global__ __launch_bounds__(K1_THREADS)
void gather_kernel(const float4* __restrict__ X4,
                   const float4* __restrict__ Ri4,
                   const float4* __restrict__ Ro4) {
    __shared__ float4 sX[K1_NPB];   // 8 KB: this block's X rows
    const int n0 = blockIdx.y * K1_NPB;
    for (int i = threadIdx.x; i < K1_NPB; i += K1_THREADS)
        sX[i] = X4[n0 + i];
    __syncthreads();

    const int rowstride = N_EDGES / 4;                       // float4s per row
    const int e4 = blockIdx.x * K1_THREADS + threadIdx.x;    // float4 col index
    const float4* ro = Ro4 + (size_t)n0 * rowstride + e4;
    const float4* ri = Ri4 + (size_t)n0 * rowstride + e4;

    float4 z = make_float4(0.f, 0.f, 0.f, 0.f);
    float4 o0 = z, o1 = z, o2 = z, o3 = z;   // bo accum for e4*4 + {0,1,2,3}
    float4 i0 = z, i1 = z, i2 = z, i3 = z;   // bi accum

    #pragma unroll 4
    for (int nl = 0; nl < K1_NPB; ++nl) {
        float4 x = sX[nl];
        float4 r = ro[(size_t)nl * rowstride];
        float4 q = ri[(size_t)nl * rowstride];
        FMA4(o0, r.x, x); FMA4(o1, r.y, x); FMA4(o2, r.z, x); FMA4(o3, r.w, x);
        FMA4(i0, q.x, x); FMA4(i1, q.y, x); FMA4(i2, q.z, x); FMA4(i3, q.w, x);
    }

    float* bo = &g_bo[(size_t)e4 * 16];
    float* bi = &g_bi[(size_t)e4 * 16];
    atomicAdd(bo + 0,  o0.x); atomicAdd(bo + 1,  o0.y); atomicAdd(bo + 2,  o0.z); atomicAdd(bo + 3,  o0.w);
    atomicAdd(bo + 4,  o1.x); atomicAdd(bo + 5,  o1.y); atomicAdd(bo + 6,  o1.z); atomicAdd(bo + 7,  o1.w);
    atomicAdd(bo + 8,  o2.x); atomicAdd(bo + 9,  o2.y); atomicAdd(bo + 10, o2.z); atomicAdd(bo + 11, o2.w);
    atomicAdd(bo + 12, o3.x); atomicAdd(bo + 13, o3.y); atomicAdd(bo + 14, o3.z); atomicAdd(bo + 15, o3.w);
    atomicAdd(bi + 0,  i0.x); atomicAdd(bi + 1,  i0.y); atomicAdd(bi + 2,  i0.z); atomicAdd(bi + 3,  i0.w);
    atomicAdd(bi + 4,  i1.x); atomicAdd(bi + 5,  i1.y); atomicAdd(bi + 6,  i1.z); atomicAdd(bi + 7,  i1.w);
    atomicAdd(bi + 8,  i2.x); atomicAdd(bi + 9,  i2.y); atomicAdd(bi + 10, i2.z); atomicAdd(bi + 11, i2.w);
    atomicAdd(bi + 12, i3.x); atomicAdd(bi + 13, i3.y); atomicAdd(bi + 14, i3.z); atomicAdd(bi + 15, i3.w);
}

// ---------------- kernel 2: per-edge scalars so/si ----------------------------
__global__ void edge_kernel(const float* __restrict__ ew,
                            const float* __restrict__ kern) {
    int e = blockIdx.x * blockDim.x + threadIdx.x;
    if (e < N_EDGES) {
        float w = ew[e];
        float4 bo = reinterpret_cast<const float4*>(g_bo)[e];
        float4 bi = reinterpret_cast<const float4*>(g_bi)[e];
        g_so[e] = w * (bo.x * kern[0] + bo.y * kern[1] + bo.z * kern[2] + bo.w * kern[3]);
        g_si[e] = w * (bi.x * kern[4] + bi.y * kern[5] + bi.z * kern[6] + bi.w * kern[7]);
    }
}

// ---------------- kernel 3: out[n] = Ri[n,:]·so + Ro[n,:]·si + X[n]·k[8:12] --
__global__ __launch_bounds__(256)
void scatter_kernel(const float4* __restrict__ Ri4,
                    const float4* __restrict__ Ro4,
                    const float4* __restrict__ X4,
                    const float* __restrict__ kern,
                    float* __restrict__ out) {
    const int n = blockIdx.x;
    const int rowstride = N_EDGES / 4;
    const float4* ri = Ri4 + (size_t)n * rowstride;
    const float4* ro = Ro4 + (size_t)n * rowstride;
    const float4* so4 = reinterpret_cast<const float4*>(g_so);
    const float4* si4 = reinterpret_cast<const float4*>(g_si);

    float s = 0.0f;
    for (int j = threadIdx.x; j < rowstride; j += 256) {
        float4 a = ri[j], w = so4[j];
        s += a.x * w.x + a.y * w.y + a.z * w.z + a.w * w.w;
        float4 b = ro[j], v = si4[j];
        s += b.x * v.x + b.y * v.y + b.z * v.z + b.w * v.w;
    }

    // block reduction: warp shuffle + smem across 8 warps
    #pragma unroll
    for (int off = 16; off > 0; off >>= 1)
        s += __shfl_down_sync(0xFFFFFFFFu, s, off);

    __shared__ float red[8];
    int wid = threadIdx.x >> 5, lid = threadIdx.x & 31;
    if (lid == 0) red[wid] = s;
    __syncthreads();
    if (wid == 0) {
        s = (lid < 8) ? red[lid] : 0.0f;
        #pragma unroll
        for (int off = 4; off > 0; off >>= 1)
            s += __shfl_down_sync(0xFFFFFFFFu, s, off);
        if (lid == 0) {
            float4 x = X4[n];
            s += x.x * kern[8] + x.y * kern[9] + x.z * kern[10] + x.w * kern[11];
            out[n] = s;
        }
    }
}

// ---------------- launch ------------------------------------------------------
extern "C" void kernel_launch(void* const* d_in, const int* in_sizes, int n_in,
                              void* d_out, int out_size) {
    const float* X    = (const float*)d_in[0];   // [8192, 4]
    const float* e    = (const float*)d_in[1];   // [16384, 1]
    const float* Ri   = (const float*)d_in[2];   // [8192, 16384]
    const float* Ro   = (const float*)d_in[3];   // [8192, 16384]
    const float* kern = (const float*)d_in[4];   // [12, 1]
    float* out = (float*)d_out;                  // [8192, 1]

    zero_kernel<<<(N_EDGES * 4 + 255) / 256, 256>>>();
    gather_kernel<<<dim3((N_EDGES / 4) / K1_THREADS, K1_NCHUNK), K1_THREADS>>>(
        (const float4*)X, (const float4*)Ri, (const float4*)Ro);
    edge_kernel<<<(N_EDGES + 255) / 256, 256>>>(e, kern);
    scatter_kernel<<<N_NODES, 256>>>(
        (const float4*)Ri, (const float4*)Ro, (const float4*)X, kern, out);
}

// round 3
// speedup vs baseline: 1.2576x; 1.2576x over previous
#include <cuda_runtime.h>

#define N_NODES 8192
#define N_EDGES 16384
#define E4      (N_EDGES / 4)      // 4096 float4 per matrix row
#define NCHUNK  32
#define ROWS_PB (N_NODES / NCHUNK) // 256 rows per gather block
#define K1_THREADS 128

// ---------------- scratch (device globals; no allocs allowed) ----------------
// Partial column-reductions: [NCHUNK][E4][4 float4] = 8 MB each. Fully
// overwritten every launch -> deterministic, no zeroing needed.
__device__ __align__(16) float4 g_pbo[(size_t)NCHUNK * E4 * 4];
__device__ __align__(16) float4 g_pbi[(size_t)NCHUNK * E4 * 4];
__device__ __align__(16) float  g_so[N_EDGES];
__device__ __align__(16) float  g_si[N_EDGES];

#define FMA4(acc, s, v) \
    acc.x += (s) * (v).x; acc.y += (s) * (v).y; \
    acc.z += (s) * (v).z; acc.w += (s) * (v).w;

// ---------------- kernel 1: partial bo = Ro^T X, bi = Ri^T X ------------------
// Grid: (E4/128 = 32, NCHUNK = 32) = 1024 blocks. Each thread owns 4
// consecutive edges (one float4 per row), accumulates over its 256-row chunk
// in registers, stores partials with plain STG.128 (no atomics).
__global__ __launch_bounds__(K1_THREADS)
void gather_kernel(const float4* __restrict__ X4,
                   const float4* __restrict__ Ri4,
                   const float4* __restrict__ Ro4) {
    __shared__ float4 sX[ROWS_PB];   // 4 KB
    const int n0 = blockIdx.y * ROWS_PB;
    for (int i = threadIdx.x; i < ROWS_PB; i += K1_THREADS)
        sX[i] = X4[n0 + i];
    __syncthreads();

    const int e4 = blockIdx.x * K1_THREADS + threadIdx.x;
    const float4* ro = Ro4 + (size_t)n0 * E4 + e4;
    const float4* ri = Ri4 + (size_t)n0 * E4 + e4;

    float4 z = make_float4(0.f, 0.f, 0.f, 0.f);
    float4 o0 = z, o1 = z, o2 = z, o3 = z;
    float4 i0 = z, i1 = z, i2 = z, i3 = z;

    #pragma unroll 8
    for (int nl = 0; nl < ROWS_PB; ++nl) {
        float4 x = sX[nl];
        float4 r = ro[(size_t)nl * E4];
        float4 q = ri[(size_t)nl * E4];
        FMA4(o0, r.x, x); FMA4(o1, r.y, x); FMA4(o2, r.z, x); FMA4(o3, r.w, x);
        FMA4(i0, q.x, x); FMA4(i1, q.y, x); FMA4(i2, q.z, x); FMA4(i3, q.w, x);
    }

    float4* pbo = g_pbo + ((size_t)blockIdx.y * E4 + e4) * 4;
    float4* pbi = g_pbi + ((size_t)blockIdx.y * E4 + e4) * 4;
    pbo[0] = o0; pbo[1] = o1; pbo[2] = o2; pbo[3] = o3;
    pbi[0] = i0; pbi[1] = i1; pbi[2] = i2; pbi[3] = i3;
}

// ---------------- kernel 2: reduce partials, compute so/si --------------------
__global__ __launch_bounds__(256)
void edge_kernel(const float* __restrict__ ew,
                 const float* __restrict__ kern) {
    int e = blockIdx.x * blockDim.x + threadIdx.x;
    if (e >= N_EDGES) return;
    const int base = e >> 2;
    const int j = e & 3;

    float4 bo = make_float4(0.f, 0.f, 0.f, 0.f);
    float4 bi = make_float4(0.f, 0.f, 0.f, 0.f);
    #pragma unroll 8
    for (int c = 0; c < NCHUNK; ++c) {
        float4 p = g_pbo[((size_t)c * E4 + base) * 4 + j];
        bo.x += p.x; bo.y += p.y; bo.z += p.z; bo.w += p.w;
        float4 q = g_pbi[((size_t)c * E4 + base) * 4 + j];
        bi.x += q.x; bi.y += q.y; bi.z += q.z; bi.w += q.w;
    }

    float w = ew[e];
    g_so[e] = w * (bo.x * kern[0] + bo.y * kern[1] + bo.z * kern[2] + bo.w * kern[3]);
    g_si[e] = w * (bi.x * kern[4] + bi.y * kern[5] + bi.z * kern[6] + bi.w * kern[7]);
}

// ---------------- kernel 3: out[n] = Ri[n,:]·so + Ro[n,:]·si + X[n]·k[8:12] --
__global__ __launch_bounds__(256)
void scatter_kernel(const float4* __restrict__ Ri4,
                    const float4* __restrict__ Ro4,
                    const float4* __restrict__ X4,
                    const float* __restrict__ kern,
                    float* __restrict__ out) {
    const int n = blockIdx.x;
    const float4* ri = Ri4 + (size_t)n * E4;
    const float4* ro = Ro4 + (size_t)n * E4;
    const float4* so4 = reinterpret_cast<const float4*>(g_so);
    const float4* si4 = reinterpret_cast<const float4*>(g_si);

    float s = 0.0f;
    #pragma unroll 4
    for (int t = 0; t < E4 / 256; ++t) {
        int j = t * 256 + threadIdx.x;
        float4 a = ri[j], w = so4[j];
        s += a.x * w.x + a.y * w.y + a.z * w.z + a.w * w.w;
        float4 b = ro[j], v = si4[j];
        s += b.x * v.x + b.y * v.y + b.z * v.z + b.w * v.w;
    }

    #pragma unroll
    for (int off = 16; off > 0; off >>= 1)
        s += __shfl_down_sync(0xFFFFFFFFu, s, off);

    __shared__ float red[8];
    int wid = threadIdx.x >> 5, lid = threadIdx.x & 31;
    if (lid == 0) red[wid] = s;
    __syncthreads();
    if (wid == 0) {
        s = (lid < 8) ? red[lid] : 0.0f;
        #pragma unroll
        for (int off = 4; off > 0; off >>= 1)
            s += __shfl_down_sync(0xFFFFFFFFu, s, off);
        if (lid == 0) {
            float4 x = X4[n];
            s += x.x * kern[8] + x.y * kern[9] + x.z * kern[10] + x.w * kern[11];
            out[n] = s;
        }
    }
}

// ---------------- launch ------------------------------------------------------
extern "C" void kernel_launch(void* const* d_in, const int* in_sizes, int n_in,
                              void* d_out, int out_size) {
    const float* X    = (const float*)d_in[0];   // [8192, 4]
    const float* e    = (const float*)d_in[1];   // [16384, 1]
    const float* Ri   = (const float*)d_in[2];   // [8192, 16384]
    const float* Ro   = (const float*)d_in[3];   // [8192, 16384]
    const float* kern = (const float*)d_in[4];   // [12, 1]
    float* out = (float*)d_out;                  // [8192, 1]

    gather_kernel<<<dim3(E4 / K1_THREADS, NCHUNK), K1_THREADS>>>(
        (const float4*)X, (const float4*)Ri, (const float4*)Ro);
    edge_kernel<<<(N_EDGES + 255) / 256, 256>>>(e, kern);
    scatter_kernel<<<N_NODES, 256>>>(
        (const float4*)Ri, (const float4*)Ro, (const float4*)X, kern, out);
}